// round 4
// baseline (speedup 1.0000x reference)
#include <cuda_runtime.h>

// 4-qubit quanvolution + linear head + log_softmax, fully fused.
// d_in[0] = x        (1024*1*28*28 f32)
// d_in[1] = q_params (3*4*3 f32)
// d_in[2] = W        (10*784 f32)
// d_in[3] = b        (10 f32)
// d_out   = log_softmax logits (1024*10 f32)

#define NTHREADS 256

__device__ __forceinline__ void apply_ry(float2* s, int m, float c, float sn) {
#pragma unroll
    for (int i = 0; i < 16; i++) {
        if ((i & m) == 0) {
            int j = i | m;
            float2 a = s[i], b = s[j];
            s[i].x = c * a.x - sn * b.x;
            s[i].y = c * a.y - sn * b.y;
            s[j].x = sn * a.x + c * b.x;
            s[j].y = sn * a.y + c * b.y;
        }
    }
}

__device__ __forceinline__ void cnot_g(float2* s, int mc, int mt) {
#pragma unroll
    for (int i = 0; i < 16; i++) {
        if ((i & mc) && !(i & mt)) {
            int j = i | mt;
            float2 tmp = s[i]; s[i] = s[j]; s[j] = tmp;
        }
    }
}

__device__ __forceinline__ void apply_u(float2* s, int m,
                                        float u0, float u1, float u2, float u3,
                                        float u4, float u5, float u6, float u7) {
#pragma unroll
    for (int i = 0; i < 16; i++) {
        if ((i & m) == 0) {
            int j = i | m;
            float2 a = s[i], b = s[j];
            float2 na, nb;
            na.x = u0 * a.x - u1 * a.y + u2 * b.x - u3 * b.y;
            na.y = u0 * a.y + u1 * a.x + u2 * b.y + u3 * b.x;
            nb.x = u4 * a.x - u5 * a.y + u6 * b.x - u7 * b.y;
            nb.y = u4 * a.y + u5 * a.x + u6 * b.y + u7 * b.x;
            s[i] = na; s[j] = nb;
        }
    }
}

__global__ __launch_bounds__(NTHREADS)
void quanv_fused_kernel(const float* __restrict__ x,
                        const float* __restrict__ qp,
                        const float* __restrict__ W,
                        const float* __restrict__ bias,
                        float* __restrict__ out) {
    __shared__ float img[784];      // one 28x28 image
    __shared__ float Umat[12][8];   // combined RZ*RY*RZ per (layer,wire)
    __shared__ float feats[784];    // 196 patches x 4 wires
    __shared__ float red[8][10];    // per-warp partial logits

    const int b = blockIdx.x;
    const int t = threadIdx.x;

    // Stage image into shared (coalesced).
    for (int i = t; i < 784; i += NTHREADS) img[i] = x[b * 784 + i];

    // Precompute the 12 combined single-qubit unitaries U = RZ(g)*RY(be)*RZ(al):
    //   u00 = cb*e^{-i(a+g)}, u01 = -sb*e^{+i(a-g)}, u10 = sb*e^{-i(a-g)}, u11 = cb*e^{+i(a+g)}
    if (t < 12) {
        float a  = 0.5f * qp[t * 3 + 0];
        float be = 0.5f * qp[t * 3 + 1];
        float g  = 0.5f * qp[t * 3 + 2];
        float cp, sp, cm, sm, cb, sb;
        sincosf(a + g, &sp, &cp);
        sincosf(a - g, &sm, &cm);
        sincosf(be, &sb, &cb);
        Umat[t][0] =  cb * cp;  Umat[t][1] = -cb * sp;   // u00 re,im
        Umat[t][2] = -sb * cm;  Umat[t][3] = -sb * sm;   // u01
        Umat[t][4] =  sb * cm;  Umat[t][5] = -sb * sm;   // u10
        Umat[t][6] =  cb * cp;  Umat[t][7] =  cb * sp;   // u11
    }
    __syncthreads();

    // ---- Phase 1: one patch per thread (196 active), statevector in registers ----
    if (t < 196) {
        const int pr = t / 14, pc = t % 14;
        float th0 = img[(2 * pr) * 28 + 2 * pc];
        float th1 = img[(2 * pr) * 28 + 2 * pc + 1];
        float th2 = img[(2 * pr + 1) * 28 + 2 * pc];
        float th3 = img[(2 * pr + 1) * 28 + 2 * pc + 1];

        float cw[4], sw[4];
        __sincosf(0.5f * th0, &sw[0], &cw[0]);
        __sincosf(0.5f * th1, &sw[1], &cw[1]);
        __sincosf(0.5f * th2, &sw[2], &cw[2]);
        __sincosf(0.5f * th3, &sw[3], &cw[3]);

        float2 s[16];
#pragma unroll
        for (int i = 0; i < 16; i++) { s[i].x = 0.0f; s[i].y = 0.0f; }
        s[0].x = 1.0f;

#pragma unroll
        for (int layer = 0; layer < 3; layer++) {
            // RY(patch angle) on each wire (wire w -> bit mask 8>>w)
#pragma unroll
            for (int w = 0; w < 4; w++) apply_ry(s, 8 >> w, cw[w], sw[w]);
            // CNOT ring 0->1, 1->2, 2->3, 3->0
            cnot_g(s, 8, 4);
            cnot_g(s, 4, 2);
            cnot_g(s, 2, 1);
            cnot_g(s, 1, 8);
            // combined RZ*RY*RZ per wire
#pragma unroll
            for (int w = 0; w < 4; w++) {
                const float* u = Umat[layer * 4 + w];
                apply_u(s, 8 >> w, u[0], u[1], u[2], u[3], u[4], u[5], u[6], u[7]);
            }
        }

        // <Z_w> expectations
        float ez0 = 0.f, ez1 = 0.f, ez2 = 0.f, ez3 = 0.f;
#pragma unroll
        for (int i = 0; i < 16; i++) {
            float p = s[i].x * s[i].x + s[i].y * s[i].y;
            ez0 += (i & 8) ? -p : p;
            ez1 += (i & 4) ? -p : p;
            ez2 += (i & 2) ? -p : p;
            ez3 += (i & 1) ? -p : p;
        }
        feats[t * 4 + 0] = ez0;
        feats[t * 4 + 1] = ez1;
        feats[t * 4 + 2] = ez2;
        feats[t * 4 + 3] = ez3;
    }
    __syncthreads();

    // ---- Phase 2: logits = feats @ W^T, coalesced over feature index ----
    float acc[10];
#pragma unroll
    for (int c = 0; c < 10; c++) acc[c] = 0.0f;

    for (int j = t; j < 784; j += NTHREADS) {
        float f = feats[j];
#pragma unroll
        for (int c = 0; c < 10; c++) acc[c] += f * W[c * 784 + j];
    }

    // deterministic warp-shuffle reduction, then fixed-order cross-warp sum
#pragma unroll
    for (int c = 0; c < 10; c++) {
        float v = acc[c];
#pragma unroll
        for (int off = 16; off > 0; off >>= 1)
            v += __shfl_down_sync(0xffffffffu, v, off);
        if ((t & 31) == 0) red[t >> 5][c] = v;
    }
    __syncthreads();

    if (t == 0) {
        float l[10];
        float m = -1e30f;
#pragma unroll
        for (int c = 0; c < 10; c++) {
            float v = bias[c];
#pragma unroll
            for (int wgp = 0; wgp < 8; wgp++) v += red[wgp][c];
            l[c] = v;
            m = fmaxf(m, v);
        }
        float sum = 0.0f;
#pragma unroll
        for (int c = 0; c < 10; c++) sum += expf(l[c] - m);
        float lse = logf(sum);
#pragma unroll
        for (int c = 0; c < 10; c++) out[b * 10 + c] = l[c] - m - lse;
    }
}

extern "C" void kernel_launch(void* const* d_in, const int* in_sizes, int n_in,
                              void* d_out, int out_size) {
    const float* x    = (const float*)d_in[0];
    const float* qp   = (const float*)d_in[1];
    const float* W    = (const float*)d_in[2];
    const float* bias = (const float*)d_in[3];
    float* out = (float*)d_out;

    int B = in_sizes[0] / 784;  // 1024
    quanv_fused_kernel<<<B, NTHREADS>>>(x, qp, W, bias, out);
}

// round 5
// speedup vs baseline: 1.2007x; 1.2007x over previous
#include <cuda_runtime.h>

// Quanvolution (4-qubit, 3 layers) + linear head + log_softmax, fully fused.
// Two images per block; every thread packs (imageA, imageB) into f32x2 lanes.
// d_in[0]=x (1024*784 f32), d_in[1]=q_params (3*4*3), d_in[2]=W (10*784), d_in[3]=b (10)
// d_out = log_softmax logits (1024*10 f32)

#define NT 256

struct pf2 { unsigned long long v; };

__device__ __forceinline__ pf2 ppack(float lo, float hi) {
    pf2 r; asm("mov.b64 %0, {%1, %2};" : "=l"(r.v) : "f"(lo), "f"(hi)); return r;
}
__device__ __forceinline__ pf2 psplat(float x) {
    pf2 r; asm("mov.b64 %0, {%1, %1};" : "=l"(r.v) : "f"(x)); return r;
}
__device__ __forceinline__ void punpack(pf2 a, float& lo, float& hi) {
    asm("mov.b64 {%0, %1}, %2;" : "=f"(lo), "=f"(hi) : "l"(a.v));
}
__device__ __forceinline__ pf2 pmul(pf2 a, pf2 b) {
    pf2 r; asm("mul.rn.f32x2 %0, %1, %2;" : "=l"(r.v) : "l"(a.v), "l"(b.v)); return r;
}
__device__ __forceinline__ pf2 padd(pf2 a, pf2 b) {
    pf2 r; asm("add.rn.f32x2 %0, %1, %2;" : "=l"(r.v) : "l"(a.v), "l"(b.v)); return r;
}
__device__ __forceinline__ pf2 pfma(pf2 a, pf2 b, pf2 c) {
    pf2 r; asm("fma.rn.f32x2 %0, %1, %2, %3;" : "=l"(r.v) : "l"(a.v), "l"(b.v), "l"(c.v)); return r;
}
__device__ __forceinline__ pf2 pneg(pf2 a) { pf2 r; r.v = a.v ^ 0x8000000080000000ULL; return r; }
__device__ __forceinline__ pf2 pzero() { pf2 r; r.v = 0ULL; return r; }

// Composite permutation of the CNOT ring 0->1,1->2,2->3,3->0 (wire w = bit 3-w).
// final[b] = pre[qperm(b)]; constant-folds under full unroll.
__device__ __forceinline__ int qperm(int b) {
    int c = b ^ ((b & 1) ? 8 : 0);
    int d = c ^ ((c & 2) ? 1 : 0);
    int e = d ^ ((d & 4) ? 2 : 0);
    return e ^ ((e & 8) ? 4 : 0);
}

// General SU(2) gate [[g, d],[-d*, g*]] on wire mask m, packed per-lane coefficients.
__device__ __forceinline__ void apply_su2(pf2* sx, pf2* sy, int m,
                                          pf2 gx, pf2 gy, pf2 dx, pf2 dy) {
    pf2 ngy = pneg(gy), ndx = pneg(dx), ndy = pneg(dy);
#pragma unroll
    for (int i = 0; i < 16; i++) {
        if (!(i & m)) {
            int j = i | m;
            pf2 ax = sx[i], ay = sy[i], bx = sx[j], by = sy[j];
            pf2 nx = pmul(gx, ax); nx = pfma(ngy, ay, nx); nx = pfma(dx, bx, nx); nx = pfma(ndy, by, nx);
            pf2 ny = pmul(gx, ay); ny = pfma(gy, ax, ny); ny = pfma(dx, by, ny); ny = pfma(dy, bx, ny);
            pf2 mx = pmul(ndx, ax); mx = pfma(ndy, ay, mx); mx = pfma(gx, bx, mx); mx = pfma(gy, by, mx);
            pf2 my = pmul(ndx, ay); my = pfma(dy, ax, my); my = pfma(gx, by, my); my = pfma(ngy, bx, my);
            sx[i] = nx; sy[i] = ny; sx[j] = mx; sy[j] = my;
        }
    }
}

// V = RY(theta) * U, with U = [[a, b],[-b*, a*]] (splat) and RY coeffs c,s (per-lane):
//   gamma = c*a + s*b*,  delta = c*b - s*a*
__device__ __forceinline__ void build_v(pf2 c, pf2 s, const float* U,
                                        pf2& gx, pf2& gy, pf2& dx, pf2& dy) {
    pf2 uax = psplat(U[0]), uay = psplat(U[1]), ubx = psplat(U[2]), uby = psplat(U[3]);
    gx = pfma(c, uax, pmul(s, ubx));
    gy = pfma(c, uay, pneg(pmul(s, uby)));
    dx = pfma(c, ubx, pneg(pmul(s, uax)));
    dy = pfma(c, uby, pmul(s, uay));
}

__device__ __forceinline__ void cnot_sw(pf2* sx, pf2* sy, int mc, int mt) {
#pragma unroll
    for (int i = 0; i < 16; i++) {
        if ((i & mc) && !(i & mt)) {
            int j = i | mt;
            pf2 t = sx[i]; sx[i] = sx[j]; sx[j] = t;
            t = sy[i]; sy[i] = sy[j]; sy[j] = t;
        }
    }
}

__global__ __launch_bounds__(NT)
void quanv2_kernel(const float* __restrict__ x, const float* __restrict__ qp,
                   const float* __restrict__ W, const float* __restrict__ bias,
                   float* __restrict__ out) {
    __shared__ float imgA[784], imgB[784];
    __shared__ float Um[12][8];                 // ax, ay, bx, by, D, EX, EYn, EYp
    __shared__ unsigned long long feats[784];   // packed (featA, featB)
    __shared__ unsigned long long red[8][10];

    const int b = blockIdx.x;
    const int t = threadIdx.x;

    const float* xb = x + (size_t)b * 1568;
    for (int i = t; i < 1568; i += NT) {
        float v = xb[i];
        if (i < 784) imgA[i] = v; else imgB[i - 784] = v;
    }

    if (t < 12) {
        float a  = 0.5f * qp[t * 3 + 0];
        float be = 0.5f * qp[t * 3 + 1];
        float g  = 0.5f * qp[t * 3 + 2];
        float cp, sp, cm, sm, cb, sb;
        sincosf(a + g, &sp, &cp);
        sincosf(a - g, &sm, &cm);
        sincosf(be, &sb, &cb);
        float ax = cb * cp, ay = -cb * sp, bx = -sb * cm, by = -sb * sm;
        Um[t][0] = ax; Um[t][1] = ay; Um[t][2] = bx; Um[t][3] = by;
        Um[t][4] = ax * ax + ay * ay - bx * bx - by * by;   // D
        float reab = ax * bx + ay * by;                     // Re(a* b)
        float imab = ax * by - ay * bx;                     // Im(a* b)
        Um[t][5] =  4.0f * reab;                            // EX
        Um[t][6] = -4.0f * imab;                            // coeff of sx_i*sy_j
        Um[t][7] =  4.0f * imab;                            // coeff of sy_i*sx_j
    }
    __syncthreads();

    if (t < 196) {
        const int pr = t / 14, pc = t % 14;
        const int i0 = (2 * pr) * 28 + 2 * pc;
        float thA[4] = { imgA[i0], imgA[i0 + 1], imgA[i0 + 28], imgA[i0 + 29] };
        float thB[4] = { imgB[i0], imgB[i0 + 1], imgB[i0 + 28], imgB[i0 + 29] };

        pf2 cw[4], sw[4];
#pragma unroll
        for (int w = 0; w < 4; w++) {
            float cA, sA, cB, sB;
            __sincosf(0.5f * thA[w], &sA, &cA);
            __sincosf(0.5f * thB[w], &sB, &cB);
            cw[w] = ppack(cA, cB);
            sw[w] = ppack(sA, sB);
        }

        // Layer-0 RY product state with CNOT ring folded in as index permutation.
        pf2 p01[4], p23[4];
        p01[0] = pmul(cw[0], cw[1]); p01[1] = pmul(cw[0], sw[1]);
        p01[2] = pmul(sw[0], cw[1]); p01[3] = pmul(sw[0], sw[1]);
        p23[0] = pmul(cw[2], cw[3]); p23[1] = pmul(cw[2], sw[3]);
        p23[2] = pmul(sw[2], cw[3]); p23[3] = pmul(sw[2], sw[3]);

        pf2 sx[16], sy[16];
#pragma unroll
        for (int i = 0; i < 16; i++) {
            int q = qperm(i);
            sx[i] = pmul(p01[q >> 2], p23[q & 3]);
        }

        // V0 = RY1 * U0. Wire 0 applied on the purely-real state (specialized).
        {
            pf2 gx, gy, dx, dy;
            build_v(cw[0], sw[0], Um[0], gx, gy, dx, dy);
            pf2 ndx = pneg(dx), ngy = pneg(gy);
#pragma unroll
            for (int i = 0; i < 8; i++) {
                int j = i | 8;
                pf2 a = sx[i], bb = sx[j];
                sx[i] = pfma(gx, a, pmul(dx, bb));
                sy[i] = pfma(gy, a, pmul(dy, bb));
                sx[j] = pfma(ndx, a, pmul(gx, bb));
                sy[j] = pfma(dy, a, pmul(ngy, bb));
            }
        }
#pragma unroll
        for (int w = 1; w < 4; w++) {
            pf2 gx, gy, dx, dy;
            build_v(cw[w], sw[w], Um[w], gx, gy, dx, dy);
            apply_su2(sx, sy, 8 >> w, gx, gy, dx, dy);
        }
        cnot_sw(sx, sy, 8, 4); cnot_sw(sx, sy, 4, 2);
        cnot_sw(sx, sy, 2, 1); cnot_sw(sx, sy, 1, 8);

        // V1 = RY2 * U1
#pragma unroll
        for (int w = 0; w < 4; w++) {
            pf2 gx, gy, dx, dy;
            build_v(cw[w], sw[w], Um[4 + w], gx, gy, dx, dy);
            apply_su2(sx, sy, 8 >> w, gx, gy, dx, dy);
        }
        cnot_sw(sx, sy, 8, 4); cnot_sw(sx, sy, 4, 2);
        cnot_sw(sx, sy, 2, 1); cnot_sw(sx, sy, 1, 8);

        // Final layer U2 folded into expectations: <Z_w> via M = U2† Z U2.
        pf2 p[16];
#pragma unroll
        for (int i = 0; i < 16; i++) p[i] = pfma(sx[i], sx[i], pmul(sy[i], sy[i]));

#pragma unroll
        for (int w = 0; w < 4; w++) {
            const float* U2 = Um[8 + w];
            pf2 sD  = psplat(U2[4]);
            pf2 snD = pneg(sD);
            pf2 sEX = psplat(U2[5]);
            pf2 sEn = psplat(U2[6]);
            pf2 sEp = psplat(U2[7]);
            const int m = 8 >> w;
            pf2 acc = pzero();
#pragma unroll
            for (int i = 0; i < 16; i++) {
                if (!(i & m)) {
                    int j = i | m;
                    acc = pfma(sD, p[i], acc);
                    acc = pfma(snD, p[j], acc);
                    pf2 rec = pfma(sx[i], sx[j], pmul(sy[i], sy[j]));
                    acc = pfma(sEX, rec, acc);
                    acc = pfma(sEn, pmul(sx[i], sy[j]), acc);
                    acc = pfma(sEp, pmul(sy[i], sx[j]), acc);
                }
            }
            feats[t * 4 + w] = acc.v;
        }
    }
    __syncthreads();

    // Phase 2: packed logits for both images.
    pf2 acc[10];
#pragma unroll
    for (int c = 0; c < 10; c++) acc[c] = pzero();

    for (int j = t; j < 784; j += NT) {
        pf2 f; f.v = feats[j];
#pragma unroll
        for (int c = 0; c < 10; c++) acc[c] = pfma(f, psplat(W[c * 784 + j]), acc[c]);
    }

#pragma unroll
    for (int c = 0; c < 10; c++) {
        pf2 v = acc[c];
#pragma unroll
        for (int off = 16; off > 0; off >>= 1) {
            pf2 o; o.v = __shfl_down_sync(0xffffffffu, v.v, off);
            v = padd(v, o);
        }
        if ((t & 31) == 0) red[t >> 5][c] = v.v;
    }
    __syncthreads();

    if (t < 2) {
        float l[10];
        float mx = -1e30f;
#pragma unroll
        for (int c = 0; c < 10; c++) {
            float s = bias[c];
#pragma unroll
            for (int wg = 0; wg < 8; wg++) {
                pf2 r; r.v = red[wg][c];
                float lo, hi; punpack(r, lo, hi);
                s += (t == 0) ? lo : hi;
            }
            l[c] = s;
            mx = fmaxf(mx, s);
        }
        float sum = 0.0f;
#pragma unroll
        for (int c = 0; c < 10; c++) sum += expf(l[c] - mx);
        float lse = logf(sum);
#pragma unroll
        for (int c = 0; c < 10; c++) out[(2 * b + t) * 10 + c] = l[c] - mx - lse;
    }
}

extern "C" void kernel_launch(void* const* d_in, const int* in_sizes, int n_in,
                              void* d_out, int out_size) {
    const float* x    = (const float*)d_in[0];
    const float* qp   = (const float*)d_in[1];
    const float* W    = (const float*)d_in[2];
    const float* bias = (const float*)d_in[3];
    float* out = (float*)d_out;

    int B2 = in_sizes[0] / 1568;  // 512 blocks, 2 images each
    quanv2_kernel<<<B2, NT>>>(x, qp, W, bias, out);
}